// round 10
// baseline (speedup 1.0000x reference)
#include <cuda_runtime.h>
#include <cuda_fp16.h>
#include <stdint.h>
#include <stddef.h>

// Problem dims (fixed by the reference)
#define T_DIM 2048
#define B_DIM 16
#define D_DIM 1024
#define M_DIM (T_DIM * B_DIM)   // 32768

// Scratch (static __device__; no cudaMalloc allowed)
__device__ float2 g_ac[(size_t)M_DIM * D_DIM];         // {alpha, c}
__device__ __half gW[(size_t)16 * 128 * D_DIM];        // remapped Wa|Wx, fp16

// ===================== common helpers =====================
static __device__ __forceinline__ uint32_t pack2(__half a, __half b) {
    return (uint32_t)__half_as_ushort(a) | ((uint32_t)__half_as_ushort(b) << 16);
}
static __device__ __forceinline__ uint32_t cvt2(float lo, float hi) {
    uint32_t r;
    asm("cvt.rn.f16x2.f32 %0, %1, %2;" : "=r"(r) : "f"(hi), "f"(lo));  // lo -> bits[0:16)
    return r;
}
static __device__ __forceinline__ uint32_t smem_u32(const void* p) {
    uint32_t a;
    asm("{ .reg .u64 t; cvta.to.shared.u64 t, %1; cvt.u32.u64 %0, t; }" : "=r"(a) : "l"(p));
    return a;
}
static __device__ __forceinline__ void cp16(uint32_t dst, const void* src) {
    asm volatile("cp.async.cg.shared.global [%0], [%1], 16;" :: "r"(dst), "l"(src) : "memory");
}
#define CP_COMMIT() asm volatile("cp.async.commit_group;" ::: "memory")
#define CP_WAIT0()  asm volatile("cp.async.wait_group 0;" ::: "memory")
#define CP_WAIT2()  asm volatile("cp.async.wait_group 2;" ::: "memory")
#define CP_WAIT5()  asm volatile("cp.async.wait_group 5;" ::: "memory")

// ===================== weight precompute =====================
// Remap weights: dest row (n>>6)*128 + m*64 + (n&63), m=0 -> Wa, m=1 -> Wx
__global__ void __launch_bounds__(256)
split_w_kernel(const float* __restrict__ Wa, const float* __restrict__ Wx) {
    const int e = blockIdx.x * 256 + threadIdx.x;   // float4 index over 2*1024*1024/4
    const int m = e >> 18;                           // 0: Wa, 1: Wx
    const int rem = e & 262143;
    const int n = rem >> 8;                          // source row
    const int c4 = rem & 255;                        // float4 col
    const float* src = m ? Wx : Wa;
    float4 v = ((const float4*)(src + (size_t)n * D_DIM))[c4];
    const size_t drow = (size_t)(n >> 6) * 128 + m * 64 + (n & 63);
    ((uint2*)gW)[drow * 256 + c4] = make_uint2(
        pack2(__float2half_rn(v.x), __float2half_rn(v.y)),
        pack2(__float2half_rn(v.z), __float2half_rn(v.w)));
}

// ===================== GEMM: BM=256; A via LDG(fp32)+cvt+STS, W via cp.async ==========
#define BK 64
#define ROWP 144                        // padded row pitch bytes (64 fp16 = 128B + 16B pad)
#define A_PART (256 * ROWP)             // 36864
#define W_PART (128 * ROWP)             // 18432
#define A_STAGES 2
#define W_STAGES 4
#define SMEM_DYN (A_STAGES * A_PART + W_STAGES * W_PART)   // 147456

#define LDSM4(R, A) \
    asm volatile("ldmatrix.sync.aligned.m8n8.x4.shared.b16 {%0,%1,%2,%3}, [%4];" \
        : "=r"((R)[0]), "=r"((R)[1]), "=r"((R)[2]), "=r"((R)[3]) : "r"(A))

static __device__ __forceinline__ void mma_fp16(float* c, const uint32_t* a, const uint32_t* b) {
    asm volatile(
        "mma.sync.aligned.m16n8k16.row.col.f32.f16.f16.f32 "
        "{%0,%1,%2,%3}, {%4,%5,%6,%7}, {%8,%9}, {%0,%1,%2,%3};\n"
        : "+f"(c[0]), "+f"(c[1]), "+f"(c[2]), "+f"(c[3])
        : "r"(a[0]), "r"(a[1]), "r"(a[2]), "r"(a[3]), "r"(b[0]), "r"(b[1]));
}

extern __shared__ char dsmem[];

__global__ void __launch_bounds__(512, 1)
gemm_mma(const float* __restrict__ x,
         const float* __restrict__ ba, const float* __restrict__ bv)
{
    const int tid = threadIdx.x;
    const int warp = tid >> 5;
    const int lane = tid & 31;
    const int n_base = blockIdx.x * 64;
    const int m_base = blockIdx.y * 256;
    const int wrow_base = blockIdx.x * 128;   // remapped weight row base

    const uint32_t sb = smem_u32(dsmem);               // A stages base
    const uint32_t wb = sb + A_STAGES * A_PART;        // W stages base

    // Per-thread A staging map: idx = tid + 512*q -> row 0..255, col-block 0..7
    const int arow = tid >> 3;         // row for q stride of 64 rows
    const int ac16 = tid & 7;          // 8-fp16 (=16B smem) column block

    // A data for one chunk, already converted: 4 x uint4 per thread
    uint4 rA[4];
    // Load fp32 (2x float4 per q) and convert immediately -> rA (held regs = 16)
#define LDG_A(KK) do {                                                                 \
    float4 v0[4], v1[4];                                                               \
    _Pragma("unroll")                                                                  \
    for (int q = 0; q < 4; q++) {                                                      \
        const int row = arow + 64 * q;                                                 \
        const float* p = &x[(size_t)(m_base + row) * D_DIM + (KK) + ac16 * 8];         \
        v0[q] = *(const float4*)p;                                                     \
        v1[q] = *(const float4*)(p + 4);                                               \
    }                                                                                  \
    _Pragma("unroll")                                                                  \
    for (int q = 0; q < 4; q++) {                                                      \
        rA[q].x = cvt2(v0[q].x, v0[q].y);                                              \
        rA[q].y = cvt2(v0[q].z, v0[q].w);                                              \
        rA[q].z = cvt2(v1[q].x, v1[q].y);                                              \
        rA[q].w = cvt2(v1[q].z, v1[q].w);                                              \
    } } while (0)

#define STS_A(SBASE) do {                                                              \
    _Pragma("unroll")                                                                  \
    for (int q = 0; q < 4; q++) {                                                      \
        const int row = arow + 64 * q;                                                 \
        *(uint4*)(dsmem + ((SBASE) - sb) + row * ROWP + ac16 * 16) = rA[q];            \
    } } while (0)

#define ISSUE_W(KK, WSLOT) do {                                                        \
    const uint32_t wdst = wb + (WSLOT) * W_PART;                                       \
    _Pragma("unroll")                                                                  \
    for (int q = 0; q < 2; q++) {                                                      \
        const int idx = tid + 512 * q;                                                 \
        const int row = idx >> 3;                                                      \
        const int c16 = idx & 7;                                                       \
        const size_t wo = ((size_t)(wrow_base + row) * D_DIM + (KK) + c16 * 8) * 2;    \
        cp16(wdst + (uint32_t)(row * ROWP + c16 * 16), (const char*)gW + wo);          \
    }                                                                                  \
    CP_COMMIT();                                                                       \
} while (0)

    // warp tiling: 16 warps; wm in {0,64,128,192}, wn in {0,16,32,48}
    const int wm = (warp >> 2) * 64;
    const int wn = (warp & 3) * 16;
    const int grp = lane >> 2;
    const int tig = lane & 3;

    float accA[4][2][4], accX[4][2][4];
#pragma unroll
    for (int i = 0; i < 4; i++)
#pragma unroll
        for (int j = 0; j < 2; j++)
#pragma unroll
            for (int r = 0; r < 4; r++) { accA[i][j][r] = 0.f; accX[i][j][r] = 0.f; }

    // ldmatrix per-lane address components
    const int rowA = ((lane >> 3) & 1) * 8 + (lane & 7);
    const int khalfA = lane >> 4;
    const int rowB = ((lane >> 4) << 3) + (lane & 7);
    const int khalfB = (lane >> 3) & 1;

    // Prologue: A chunk0 -> regs -> smem stage0; A chunk1 -> regs; W chunks 0..2 in flight
    LDG_A(0);
    ISSUE_W(0, 0);
    ISSUE_W(BK, 1);
    ISSUE_W(2 * BK, 2);
    STS_A(sb);
    LDG_A(BK);

    for (int kc = 0; kc < 16; kc++) {
        CP_WAIT2();           // W group kc landed (kc+1, kc+2 may be pending)
        __syncthreads();      // A STS of chunk kc visible; all warps done with stage (kc-1)
        if (kc + 1 < 16)
            STS_A(sb + ((kc + 1) & 1) * A_PART);     // chunk kc+1 from regs
        if (kc + 2 < 16)
            LDG_A((kc + 2) * BK);                     // chunk kc+2 into regs (load+cvt)
        if (kc + 3 < 16) {
            ISSUE_W((kc + 3) * BK, (kc + 3) & 3);     // includes commit
        } else {
            CP_COMMIT();                              // keep one group per iteration
        }

        const uint32_t aStage = sb + (kc & 1) * A_PART;
        const uint32_t wStage = wb + (kc & 3) * W_PART;
        const uint32_t aBase = aStage + (uint32_t)((wm + rowA) * ROWP + khalfA * 16);
        const uint32_t bBase = wStage + (uint32_t)((wn + rowB) * ROWP + khalfB * 16);

#pragma unroll
        for (int ks = 0; ks < 4; ks++) {
            const uint32_t ka = aBase + ks * 32;
            const uint32_t kb = bBase + ks * 32;
            uint32_t ah[4][4];
#pragma unroll
            for (int i = 0; i < 4; i++)
                LDSM4(ah[i], ka + i * (16 * ROWP));
            uint32_t bA[4], bX[4];
            LDSM4(bA, kb);                         // Wa rows (0..63)
            LDSM4(bX, kb + 64 * ROWP);             // Wx rows (64..127)
#pragma unroll
            for (int i = 0; i < 4; i++)
#pragma unroll
                for (int j = 0; j < 2; j++) {
                    mma_fp16(accA[i][j], ah[i], &bA[j * 2]);
                    mma_fp16(accX[i][j], ah[i], &bX[j * 2]);
                }
        }
    }
    CP_WAIT0();
#undef LDG_A
#undef STS_A
#undef ISSUE_W

    // Epilogue: alpha = sigmoid(uA + ba); c = (1-alpha)*tanh(uX + bv)
#pragma unroll
    for (int i = 0; i < 4; i++)
#pragma unroll
        for (int j = 0; j < 2; j++) {
            const int mrow = m_base + wm + i * 16 + grp;
            const int ncol = n_base + wn + j * 8 + tig * 2;
            const float ba0 = ba[ncol], ba1 = ba[ncol + 1];
            const float bv0 = bv[ncol], bv1 = bv[ncol + 1];
#pragma unroll
            for (int half = 0; half < 2; half++) {
                const int m = mrow + half * 8;
                float uA0 = accA[i][j][half * 2 + 0] + ba0;
                float uA1 = accA[i][j][half * 2 + 1] + ba1;
                float uX0 = accX[i][j][half * 2 + 0] + bv0;
                float uX1 = accX[i][j][half * 2 + 1] + bv1;
                float al0 = 1.0f / (1.0f + __expf(-uA0));
                float al1 = 1.0f / (1.0f + __expf(-uA1));
                float c0v = (1.0f - al0) * tanhf(uX0);
                float c1v = (1.0f - al1) * tanhf(uX1);
                g_ac[(size_t)m * D_DIM + ncol]     = make_float2(al0, c0v);
                g_ac[(size_t)m * D_DIM + ncol + 1] = make_float2(al1, c1v);
            }
        }
}

// ===================== Sequential scan: cp.async deep pipeline (unchanged, passing) =====
#define SNB 6
#define SCH 16

__global__ void __launch_bounds__(64)
scan_kernel(const float* __restrict__ dgv, const float* __restrict__ bgv,
            float* __restrict__ outs, float* __restrict__ hout, int writeH)
{
    __shared__ float2 sbuf[SNB][SCH][64];
    const int S = B_DIM * D_DIM;   // 16384 columns
    const int tid = threadIdx.x;
    const int j0 = blockIdx.x * 64;
    const int j = j0 + tid;
    const int dcol = j & (D_DIM - 1);
    const float dg  = dgv[dcol];
    const float nbg = -bgv[dcol];

#define SC_ISSUE(slot, t0) do {                                                  \
    _Pragma("unroll")                                                            \
    for (int q = 0; q < 8; q++) {                                                \
        const int idx = tid + 64 * q;                                            \
        const int row = idx >> 5;        /* 0..15 */                             \
        const int ch  = idx & 31;        /* 0..31 (16B chunks) */                \
        cp16(smem_u32(&sbuf[slot][row][ch * 2]),                                 \
             (const char*)&g_ac[(size_t)((t0) + row) * S + j0 + ch * 2]);        \
    }                                                                            \
    CP_COMMIT();                                                                 \
} while (0)

    float h = 0.0f;
    if (writeH) hout[j] = 0.0f;

#pragma unroll
    for (int s = 0; s < SNB; s++)
        SC_ISSUE(s, s * SCH);

    for (int k = 0; k < T_DIM / SCH; k++) {
        CP_WAIT5();
        __syncthreads();
        const int slot = k % SNB;
#pragma unroll
        for (int i = 0; i < SCH; i++) {
            const float2 ac = sbuf[slot][i][tid];
            const int t = k * SCH + i;
            const float alpha = ac.x, cf = ac.y;
            const float earg = fmaf(dg, fabsf(h), nbg);            // d_g|h| - b_g
            const float g = __fdividef(1.0f, 1.0f + __expf(earg)); // sigmoid(b_g - d_g|h|)
            const float hn = fmaf(cf, g, alpha * h);
            const float sg = __fdividef(1.0f, 1.0f + __expf(-hn));
            outs[(size_t)t * S + j] = hn * hn * sg;
            if (writeH) hout[(size_t)(t + 1) * S + j] = hn;
            h = hn;
        }
        __syncthreads();
        // refill this slot (dummy t0=0 reload once past the end; never consumed)
        int tn = (k + SNB) * SCH;
        if (tn > T_DIM - SCH) tn = 0;
        SC_ISSUE(slot, tn);
    }
    CP_WAIT0();
#undef SC_ISSUE
}

// ========================= launch =========================
extern "C" void kernel_launch(void* const* d_in, const int* in_sizes, int n_in,
                              void* d_out, int out_size)
{
    const float* x  = (const float*)d_in[0];
    const float* Wa = (const float*)d_in[1];
    const float* ba = (const float*)d_in[2];
    const float* dg = (const float*)d_in[3];
    const float* bg = (const float*)d_in[4];
    const float* Wx = (const float*)d_in[5];
    const float* bv = (const float*)d_in[6];

    float* out  = (float*)d_out;
    float* outs = out;
    float* hout = out + (size_t)M_DIM * D_DIM;
    const int writeH = (out_size > M_DIM * D_DIM) ? 1 : 0;

    // Precompute: remapped weights -> fp16 (x conversion is fused into the GEMM loader)
    split_w_kernel<<<(2 * D_DIM * D_DIM / 4) / 256, 256>>>(Wa, Wx);

    static int smem_set = 0;
    if (!smem_set) {
        cudaFuncSetAttribute(gemm_mma, cudaFuncAttributeMaxDynamicSharedMemorySize, SMEM_DYN);
        smem_set = 1;
    }
    dim3 grid(D_DIM / 64, M_DIM / 256);   // (16, 128), N fastest for x L2 reuse
    gemm_mma<<<grid, 512, SMEM_DYN>>>(x, ba, bv);

    scan_kernel<<<256, 64>>>(dg, bg, outs, hout, writeH);
}

// round 12
// speedup vs baseline: 1.1888x; 1.1888x over previous
#include <cuda_runtime.h>
#include <cuda_fp16.h>
#include <stdint.h>
#include <stddef.h>

// Problem dims (fixed by the reference)
#define T_DIM 2048
#define B_DIM 16
#define D_DIM 1024
#define M_DIM (T_DIM * B_DIM)   // 32768

// Scratch (static __device__; no cudaMalloc allowed)
__device__ float2 g_ac[(size_t)M_DIM * D_DIM];         // {alpha, c}
__device__ __half gXh[(size_t)M_DIM * D_DIM];          // x (fp16 rn)
__device__ __half gW[(size_t)16 * 128 * D_DIM];        // remapped Wa|Wx, fp16

// ===================== common helpers =====================
static __device__ __forceinline__ uint32_t pack2(__half a, __half b) {
    return (uint32_t)__half_as_ushort(a) | ((uint32_t)__half_as_ushort(b) << 16);
}
static __device__ __forceinline__ uint32_t smem_u32(const void* p) {
    uint32_t a;
    asm("{ .reg .u64 t; cvta.to.shared.u64 t, %1; cvt.u32.u64 %0, t; }" : "=r"(a) : "l"(p));
    return a;
}
static __device__ __forceinline__ void cp16(uint32_t dst, const void* src) {
    asm volatile("cp.async.cg.shared.global [%0], [%1], 16;" :: "r"(dst), "l"(src) : "memory");
}
#define CP_COMMIT() asm volatile("cp.async.commit_group;" ::: "memory")
#define CP_WAIT0()  asm volatile("cp.async.wait_group 0;" ::: "memory")
#define CP_WAIT2()  asm volatile("cp.async.wait_group 2;" ::: "memory")
#define CP_WAIT7()  asm volatile("cp.async.wait_group 7;" ::: "memory")

// ===================== fused precompute: split x AND remap weights =====================
// x: 32768*1024 floats = 8,388,608 float4 -> 32768 blocks of 256 threads.
// W: 2*1024*1024 floats = 524,288 float4 -> 2048 blocks.
#define XBLOCKS 32768
#define WBLOCKS 2048

__global__ void __launch_bounds__(256)
split_all_kernel(const float* __restrict__ x,
                 const float* __restrict__ Wa, const float* __restrict__ Wx) {
    if (blockIdx.x < XBLOCKS) {
        const size_t idx = (size_t)blockIdx.x * 256 + threadIdx.x;  // float4 index
        float4 v = ((const float4*)x)[idx];
        ((uint2*)gXh)[idx] = make_uint2(
            pack2(__float2half_rn(v.x), __float2half_rn(v.y)),
            pack2(__float2half_rn(v.z), __float2half_rn(v.w)));
    } else {
        const int e = (blockIdx.x - XBLOCKS) * 256 + threadIdx.x;  // float4 idx
        const int m = e >> 18;                           // 0: Wa, 1: Wx
        const int rem = e & 262143;
        const int n = rem >> 8;                          // source row
        const int c4 = rem & 255;                        // float4 col
        const float* src = m ? Wx : Wa;
        float4 v = ((const float4*)(src + (size_t)n * D_DIM))[c4];
        const size_t drow = (size_t)(n >> 6) * 128 + m * 64 + (n & 63);
        ((uint2*)gW)[drow * 256 + c4] = make_uint2(
            pack2(__float2half_rn(v.x), __float2half_rn(v.y)),
            pack2(__float2half_rn(v.z), __float2half_rn(v.w)));
    }
}

// ===================== GEMM: BM=256, A via LDG+STS (fp16), W via cp.async =====================
#define BK 64
#define ROWP 144                        // padded row pitch bytes (64 fp16 = 128B + 16B pad)
#define A_PART (256 * ROWP)             // 36864
#define W_PART (128 * ROWP)             // 18432
#define A_STAGES 2
#define W_STAGES 4
#define SMEM_DYN (A_STAGES * A_PART + W_STAGES * W_PART)   // 147456

#define LDSM4(R, A) \
    asm volatile("ldmatrix.sync.aligned.m8n8.x4.shared.b16 {%0,%1,%2,%3}, [%4];" \
        : "=r"((R)[0]), "=r"((R)[1]), "=r"((R)[2]), "=r"((R)[3]) : "r"(A))

static __device__ __forceinline__ void mma_fp16(float* c, const uint32_t* a, const uint32_t* b) {
    asm volatile(
        "mma.sync.aligned.m16n8k16.row.col.f32.f16.f16.f32 "
        "{%0,%1,%2,%3}, {%4,%5,%6,%7}, {%8,%9}, {%0,%1,%2,%3};\n"
        : "+f"(c[0]), "+f"(c[1]), "+f"(c[2]), "+f"(c[3])
        : "r"(a[0]), "r"(a[1]), "r"(a[2]), "r"(a[3]), "r"(b[0]), "r"(b[1]));
}

extern __shared__ char dsmem[];

__global__ void __launch_bounds__(512, 1)
gemm_mma(const float* __restrict__ ba, const float* __restrict__ bv)
{
    const int tid = threadIdx.x;
    const int warp = tid >> 5;
    const int lane = tid & 31;
    const int n_base = blockIdx.x * 64;
    const int m_base = blockIdx.y * 256;
    const int wrow_base = blockIdx.x * 128;   // remapped weight row base

    const uint32_t sb = smem_u32(dsmem);               // A stages base
    const uint32_t wb = sb + A_STAGES * A_PART;        // W stages base

    // Per-thread A staging map: idx = tid + 512*q -> row 0..255, col-block 0..7
    const int arow = tid >> 3;         // row for q stride of 64 rows
    const int ac16 = tid & 7;

    // A data for one chunk: 4 x uint4 per thread (32 KB of payload)
    uint4 rA[4];
#define LDG_A(KK) do {                                                                \
    _Pragma("unroll")                                                                 \
    for (int q = 0; q < 4; q++) {                                                     \
        const int row = arow + 64 * q;                                                \
        rA[q] = *(const uint4*)&gXh[(size_t)(m_base + row) * D_DIM + (KK) + ac16 * 8];\
    } } while (0)

#define STS_A(SBASE) do {                                                             \
    _Pragma("unroll")                                                                 \
    for (int q = 0; q < 4; q++) {                                                     \
        const int row = arow + 64 * q;                                                \
        *(uint4*)(dsmem + ((SBASE) - sb) + row * ROWP + ac16 * 16) = rA[q];           \
    } } while (0)

#define ISSUE_W(KK, WSLOT) do {                                                       \
    const uint32_t wdst = wb + (WSLOT) * W_PART;                                      \
    _Pragma("unroll")                                                                 \
    for (int q = 0; q < 2; q++) {                                                     \
        const int idx = tid + 512 * q;                                                \
        const int row = idx >> 3;                                                     \
        const int c16 = idx & 7;                                                      \
        const size_t wo = ((size_t)(wrow_base + row) * D_DIM + (KK) + c16 * 8) * 2;   \
        cp16(wdst + (uint32_t)(row * ROWP + c16 * 16), (const char*)gW + wo);         \
    }                                                                                 \
    CP_COMMIT();                                                                      \
} while (0)

    // warp tiling: 16 warps; wm in {0,64,128,192}, wn in {0,16,32,48}
    const int wm = (warp >> 2) * 64;
    const int wn = (warp & 3) * 16;
    const int grp = lane >> 2;
    const int tig = lane & 3;

    float accA[4][2][4], accX[4][2][4];
#pragma unroll
    for (int i = 0; i < 4; i++)
#pragma unroll
        for (int j = 0; j < 2; j++)
#pragma unroll
            for (int r = 0; r < 4; r++) { accA[i][j][r] = 0.f; accX[i][j][r] = 0.f; }

    // ldmatrix per-lane address components
    const int rowA = ((lane >> 3) & 1) * 8 + (lane & 7);
    const int khalfA = lane >> 4;
    const int rowB = ((lane >> 4) << 3) + (lane & 7);
    const int khalfB = (lane >> 3) & 1;

    // Prologue: A chunk0 -> regs -> smem stage0; A chunk1 -> regs; W chunks 0..2 in flight
    LDG_A(0);
    ISSUE_W(0, 0);
    ISSUE_W(BK, 1);
    ISSUE_W(2 * BK, 2);
    STS_A(sb);
    LDG_A(BK);

    for (int kc = 0; kc < 16; kc++) {
        CP_WAIT2();           // W group kc landed (kc+1, kc+2 may be pending)
        __syncthreads();      // A STS of chunk kc visible; all warps done with stage (kc-1)
        if (kc + 1 < 16)
            STS_A(sb + ((kc + 1) & 1) * A_PART);     // chunk kc+1 from regs
        if (kc + 2 < 16)
            LDG_A((kc + 2) * BK);                     // chunk kc+2 into regs
        if (kc + 3 < 16) {
            ISSUE_W((kc + 3) * BK, (kc + 3) & 3);     // includes commit
        } else {
            CP_COMMIT();                              // keep one group per iteration
        }

        const uint32_t aStage = sb + (kc & 1) * A_PART;
        const uint32_t wStage = wb + (kc & 3) * W_PART;
        const uint32_t aBase = aStage + (uint32_t)((wm + rowA) * ROWP + khalfA * 16);
        const uint32_t bBase = wStage + (uint32_t)((wn + rowB) * ROWP + khalfB * 16);

#pragma unroll
        for (int ks = 0; ks < 4; ks++) {
            const uint32_t ka = aBase + ks * 32;
            const uint32_t kb = bBase + ks * 32;
            uint32_t ah[4][4];
#pragma unroll
            for (int i = 0; i < 4; i++)
                LDSM4(ah[i], ka + i * (16 * ROWP));
            uint32_t bA[4], bX[4];
            LDSM4(bA, kb);                         // Wa rows (0..63)
            LDSM4(bX, kb + 64 * ROWP);             // Wx rows (64..127)
#pragma unroll
            for (int i = 0; i < 4; i++)
#pragma unroll
                for (int j = 0; j < 2; j++) {
                    mma_fp16(accA[i][j], ah[i], &bA[j * 2]);
                    mma_fp16(accX[i][j], ah[i], &bX[j * 2]);
                }
        }
    }
    CP_WAIT0();
#undef LDG_A
#undef STS_A
#undef ISSUE_W

    // Epilogue: alpha = sigmoid(uA + ba); c = (1-alpha)*tanh(uX + bv)
    // Two adjacent float2 -> one 16B store (ncol is even).
#pragma unroll
    for (int i = 0; i < 4; i++)
#pragma unroll
        for (int j = 0; j < 2; j++) {
            const int mrow = m_base + wm + i * 16 + grp;
            const int ncol = n_base + wn + j * 8 + tig * 2;
            const float ba0 = ba[ncol], ba1 = ba[ncol + 1];
            const float bv0 = bv[ncol], bv1 = bv[ncol + 1];
#pragma unroll
            for (int half = 0; half < 2; half++) {
                const int m = mrow + half * 8;
                float uA0 = accA[i][j][half * 2 + 0] + ba0;
                float uA1 = accA[i][j][half * 2 + 1] + ba1;
                float uX0 = accX[i][j][half * 2 + 0] + bv0;
                float uX1 = accX[i][j][half * 2 + 1] + bv1;
                float al0 = 1.0f / (1.0f + __expf(-uA0));
                float al1 = 1.0f / (1.0f + __expf(-uA1));
                float c0v = (1.0f - al0) * tanhf(uX0);
                float c1v = (1.0f - al1) * tanhf(uX1);
                float4 st = make_float4(al0, c0v, al1, c1v);
                *(float4*)&g_ac[(size_t)m * D_DIM + ncol] = st;
            }
        }
}

// ===================== Sequential scan: 8-stage cp.async ring (dynamic smem) =====
#define SNB 8
#define SCH 16
#define SCAN_SMEM (SNB * SCH * 64 * (int)sizeof(float2))   // 65536

__global__ void __launch_bounds__(64)
scan_kernel(const float* __restrict__ dgv, const float* __restrict__ bgv,
            float* __restrict__ outs, float* __restrict__ hout, int writeH)
{
    extern __shared__ float2 sdyn[];
    float2 (*sbuf)[SCH][64] = (float2(*)[SCH][64])sdyn;
    const int S = B_DIM * D_DIM;   // 16384 columns
    const int tid = threadIdx.x;
    const int j0 = blockIdx.x * 64;
    const int j = j0 + tid;
    const int dcol = j & (D_DIM - 1);
    const float dg  = dgv[dcol];
    const float nbg = -bgv[dcol];

#define SC_ISSUE(slot, t0) do {                                                  \
    _Pragma("unroll")                                                            \
    for (int q = 0; q < 8; q++) {                                                \
        const int idx = tid + 64 * q;                                            \
        const int row = idx >> 5;        /* 0..15 */                             \
        const int ch  = idx & 31;        /* 0..31 (16B chunks) */                \
        cp16(smem_u32(&sbuf[slot][row][ch * 2]),                                 \
             (const char*)&g_ac[(size_t)((t0) + row) * S + j0 + ch * 2]);        \
    }                                                                            \
    CP_COMMIT();                                                                 \
} while (0)

    float h = 0.0f;
    if (writeH) hout[j] = 0.0f;

#pragma unroll
    for (int s = 0; s < SNB; s++)
        SC_ISSUE(s, s * SCH);

    for (int k = 0; k < T_DIM / SCH; k++) {
        CP_WAIT7();
        __syncthreads();
        const int slot = k % SNB;
#pragma unroll
        for (int i = 0; i < SCH; i++) {
            const float2 ac = sbuf[slot][i][tid];
            const int t = k * SCH + i;
            const float alpha = ac.x, cf = ac.y;
            const float earg = fmaf(dg, fabsf(h), nbg);            // d_g|h| - b_g
            const float g = __fdividef(1.0f, 1.0f + __expf(earg)); // sigmoid(b_g - d_g|h|)
            const float hn = fmaf(cf, g, alpha * h);
            const float sg = __fdividef(1.0f, 1.0f + __expf(-hn));
            outs[(size_t)t * S + j] = hn * hn * sg;
            if (writeH) hout[(size_t)(t + 1) * S + j] = hn;
            h = hn;
        }
        __syncthreads();
        // refill this slot (dummy t0=0 reload once past the end; never consumed)
        int tn = (k + SNB) * SCH;
        if (tn > T_DIM - SCH) tn = 0;
        SC_ISSUE(slot, tn);
    }
    CP_WAIT0();
#undef SC_ISSUE
}

// ========================= launch =========================
extern "C" void kernel_launch(void* const* d_in, const int* in_sizes, int n_in,
                              void* d_out, int out_size)
{
    const float* x  = (const float*)d_in[0];
    const float* Wa = (const float*)d_in[1];
    const float* ba = (const float*)d_in[2];
    const float* dg = (const float*)d_in[3];
    const float* bg = (const float*)d_in[4];
    const float* Wx = (const float*)d_in[5];
    const float* bv = (const float*)d_in[6];

    float* out  = (float*)d_out;
    float* outs = out;
    float* hout = out + (size_t)M_DIM * D_DIM;
    const int writeH = (out_size > M_DIM * D_DIM) ? 1 : 0;

    static int attr_set = 0;
    if (!attr_set) {
        cudaFuncSetAttribute(gemm_mma, cudaFuncAttributeMaxDynamicSharedMemorySize, SMEM_DYN);
        cudaFuncSetAttribute(scan_kernel, cudaFuncAttributeMaxDynamicSharedMemorySize, SCAN_SMEM);
        attr_set = 1;
    }

    // Precompute: x -> fp16 and remapped weights -> fp16, one kernel
    split_all_kernel<<<XBLOCKS + WBLOCKS, 256>>>(x, Wa, Wx);

    dim3 grid(D_DIM / 64, M_DIM / 256);   // (16, 128), N fastest for x L2 reuse
    gemm_mma<<<grid, 512, SMEM_DYN>>>(ba, bv);

    scan_kernel<<<256, 64, SCAN_SMEM>>>(dg, bg, outs, hout, writeH);
}